// round 6
// baseline (speedup 1.0000x reference)
#include <cuda_runtime.h>

#define BB     256
#define HH     512
#define CTXL   512
#define PREDL  64
#define KC     16
#define GRID_X 128
#define NTHR   256
#define NTHR2  512

typedef unsigned long long u64;
typedef unsigned int u32;

// ---------------- persistent device state ------------------------------------------------------
__device__ float g_h0[2][HH][BB];   // [buf][k][b]
__device__ float g_h1[2][HH][BB];
__device__ float g_scale[BB];
__device__ float g_inv[BB];

struct __align__(16) Smem {
    float As0[2][KC][64];            // A chunk (h0) [buf][kk][row]
    float As1[2][KC][64];            // A chunk (h1)
    union {
        float Bs[3][2][16][KC][4];   // [mat][buf][col][kk][gate-slot]; 24 KB
        u64   xch[256][6];           // accumulator exchange (aliased after GEMM)
    } u;
    float xv[64];
    float wih0[48];
    float bih0s[48], bhh0s[48], bih1s[48], bhh1s[48];
};

__device__ __forceinline__ float sigf(float x) {
    return __fdividef(1.0f, 1.0f + __expf(-x));
}
__device__ __forceinline__ float tanh_f(float x) {
    return 2.0f * __fdividef(1.0f, 1.0f + __expf(-2.0f * x)) - 1.0f;
}

// ---------------- packed f32x2 + LDS helpers ---------------------------------------------------
__device__ __forceinline__ void lds_v2u64(u64& lo, u64& hi, u32 addr) {
    asm volatile("ld.shared.v2.u64 {%0, %1}, [%2];" : "=l"(lo), "=l"(hi) : "r"(addr));
}
__device__ __forceinline__ void lds_v4u32(u32& x, u32& y, u32& z, u32& w, u32 addr) {
    asm volatile("ld.shared.v4.b32 {%0, %1, %2, %3}, [%4];"
                 : "=r"(x), "=r"(y), "=r"(z), "=r"(w) : "r"(addr));
}
__device__ __forceinline__ void lds_v2u32(u32& x, u32& y, u32 addr) {
    asm volatile("ld.shared.v2.b32 {%0, %1}, [%2];" : "=r"(x), "=r"(y) : "r"(addr));
}
__device__ __forceinline__ u32 lds_u32(u32 addr) {
    u32 v;
    asm volatile("ld.shared.b32 %0, [%1];" : "=r"(v) : "r"(addr));
    return v;
}
__device__ __forceinline__ u64 pack2(u32 v) {
    u64 r;
    asm("mov.b64 %0, {%1, %1};" : "=l"(r) : "r"(v));
    return r;
}
__device__ __forceinline__ void ffma2(u64& d, u64 a, u64 b) {
    asm("fma.rn.f32x2 %0, %1, %2, %3;" : "=l"(d) : "l"(a), "l"(b), "l"(d));
}
__device__ __forceinline__ u64 addf2(u64 a, u64 b) {
    u64 d;
    asm("add.rn.f32x2 %0, %1, %2;" : "=l"(d) : "l"(a), "l"(b));
    return d;
}
__device__ __forceinline__ void unpack2(float& lo, float& hi, u64 v) {
    u32 l, h;
    asm("mov.b64 {%0, %1}, %2;" : "=r"(l), "=r"(h) : "l"(v));
    lo = __uint_as_float(l);
    hi = __uint_as_float(h);
}

// ---------------- register-resident GRU cells (wt = tid & 255) ---------------------------------
__device__ __forceinline__ void cell0_reg(Smem& sm, const u64* acc0, int src, int dst,
                                          int b0, int j0, int wt)
{
    const int tr = wt & 15;
    const int tc = wt >> 4;
    const int j = j0 + tc;
    float hr[4], hz[4], hn[4];
    unpack2(hr[0], hr[1], acc0[0]); unpack2(hr[2], hr[3], acc0[1]);
    unpack2(hz[0], hz[1], acc0[2]); unpack2(hz[2], hz[3], acc0[3]);
    unpack2(hn[0], hn[1], acc0[4]); unpack2(hn[2], hn[3], acc0[5]);
    const float wr = sm.wih0[tc],  wz = sm.wih0[16 + tc],  wn = sm.wih0[32 + tc];
    const float br = sm.bih0s[tc], bz = sm.bih0s[16 + tc], bn = sm.bih0s[32 + tc];
    const float cr = sm.bhh0s[tc], cz = sm.bhh0s[16 + tc], cn = sm.bhh0s[32 + tc];
    float4 xvv = *reinterpret_cast<const float4*>(&sm.xv[4 * tr]);
    float4 hp  = *reinterpret_cast<const float4*>(&g_h0[src][j][b0 + 4 * tr]);
    const float xa[4] = {xvv.x, xvv.y, xvv.z, xvv.w};
    const float ha[4] = {hp.x, hp.y, hp.z, hp.w};
    float o[4];
#pragma unroll
    for (int i = 0; i < 4; i++) {
        float r = sigf(fmaf(xa[i], wr, br) + hr[i] + cr);
        float z = sigf(fmaf(xa[i], wz, bz) + hz[i] + cz);
        float n = tanh_f(fmaf(xa[i], wn, bn) + r * (hn[i] + cn));
        o[i] = (1.f - z) * n + z * ha[i];
    }
    *reinterpret_cast<float4*>(&g_h0[dst][j][b0 + 4 * tr]) = make_float4(o[0], o[1], o[2], o[3]);
}

__device__ __forceinline__ void cell1_reg(Smem& sm, const u64* acc1, const u64* acc2,
                                          int src, int dst, int b0, int j0, int wt)
{
    const int tr = wt & 15;
    const int tc = wt >> 4;
    const int j = j0 + tc;
    float xr[4], xz[4], xn[4], hr[4], hz[4], hn[4];
    unpack2(xr[0], xr[1], acc1[0]); unpack2(xr[2], xr[3], acc1[1]);
    unpack2(xz[0], xz[1], acc1[2]); unpack2(xz[2], xz[3], acc1[3]);
    unpack2(xn[0], xn[1], acc1[4]); unpack2(xn[2], xn[3], acc1[5]);
    unpack2(hr[0], hr[1], acc2[0]); unpack2(hr[2], hr[3], acc2[1]);
    unpack2(hz[0], hz[1], acc2[2]); unpack2(hz[2], hz[3], acc2[3]);
    unpack2(hn[0], hn[1], acc2[4]); unpack2(hn[2], hn[3], acc2[5]);
    const float br = sm.bih1s[tc], bz = sm.bih1s[16 + tc], bn = sm.bih1s[32 + tc];
    const float cr = sm.bhh1s[tc], cz = sm.bhh1s[16 + tc], cn = sm.bhh1s[32 + tc];
    float4 hp = *reinterpret_cast<const float4*>(&g_h1[src][j][b0 + 4 * tr]);
    const float ha[4] = {hp.x, hp.y, hp.z, hp.w};
    float o[4];
#pragma unroll
    for (int i = 0; i < 4; i++) {
        float r = sigf(xr[i] + br + hr[i] + cr);
        float z = sigf(xz[i] + bz + hz[i] + cz);
        float n = tanh_f(xn[i] + bn + r * (hn[i] + cn));
        o[i] = (1.f - z) * n + z * ha[i];
    }
    *reinterpret_cast<float4*>(&g_h1[dst][j][b0 + 4 * tr]) = make_float4(o[0], o[1], o[2], o[3]);
}

// ---------------- kernel 1: init ---------------------------------------------------------------
__global__ void __launch_bounds__(NTHR)
k_init(const float* __restrict__ ctx)
{
    __shared__ float red[8];
    const int tid = threadIdx.x;
    const int bid = blockIdx.x;
    {
        const int total = 2 * HH * BB;
        float* z0 = &g_h0[0][0][0];
        float* z1 = &g_h1[0][0][0];
        for (int i = bid * NTHR + tid; i < total; i += GRID_X * NTHR) {
            z0[i] = 0.f;
            z1[i] = 0.f;
        }
    }
    const int b = 2 * bid + (tid >> 7);
    const int t = tid & 127;
    float s = 0.f;
#pragma unroll
    for (int q = 0; q < 4; q++) s += ctx[b * CTXL + t + 128 * q];
#pragma unroll
    for (int o = 16; o; o >>= 1) s += __shfl_xor_sync(0xffffffffu, s, o);
    if ((tid & 31) == 0) red[tid >> 5] = s;
    __syncthreads();
    if ((tid & 127) == 0) {
        int w0 = (tid >> 5);
        float m = (red[w0] + red[w0 + 1] + red[w0 + 2] + red[w0 + 3]) * (1.f / CTXL);
        float sc = fmaxf(fabsf(m), 1e-5f);
        g_scale[b] = sc;
        g_inv[b] = __fdividef(1.0f, sc);
    }
}

// ---------------- kernel 2: encoder phase ------------------------------------------------------
// wg0: acc0 = h0 x Whh0 (r,z,n) + accR = h0 x Wih1 (r gate)
// wg1: acc2 = h1 x Whh1 (r,z,n) + acc1[z,n] = h0 x Wih1 (z,n gates)
// B slots: Bs[0]=Whh0 [r,z,n,-]; Bs[1]=Wih1 [z,n,r,-]; Bs[2]=Whh1 [r,z,n,-]
__global__ void __launch_bounds__(NTHR2)
k_enc(const float* __restrict__ ctx,
      const float* __restrict__ Wih0, const float* __restrict__ Whh0,
      const float* __restrict__ bih0, const float* __restrict__ bhh0,
      const float* __restrict__ Wih1, const float* __restrict__ Whh1,
      const float* __restrict__ bih1, const float* __restrict__ bhh1,
      int p)
{
    __shared__ Smem sm;
    const int tid = threadIdx.x;
    const int wg = tid >> 8;
    const int wt = tid & 255;
    const int bid = blockIdx.x;
    const int b0 = (bid >> 5) * 64;
    const int j0 = (bid & 31) * 16;
    const int src = (p + 1) & 1, dst = p & 1;

    if (tid < 48) {
        int g = (tid >> 4) * HH + j0 + (tid & 15);
        sm.wih0[tid]  = Wih0[g];
        sm.bih0s[tid] = bih0[g];
        sm.bhh0s[tid] = bhh0[g];
        sm.bih1s[tid] = bih1[g];
        sm.bhh1s[tid] = bhh1[g];
    }
    if (p < CTXL && tid < 64)
        sm.xv[tid] = ctx[(b0 + tid) * CTXL + p] * g_inv[b0 + tid];

    const float* A0 = &g_h0[src][0][b0];
    const float* A1 = &g_h1[src][0][b0];

    const int ar = wt & 63, ak0 = wt >> 6;          // A-loader coords
    const int bcol = wt >> 4, bkk = wt & 15;        // B-loader coords
    const int tr = wt & 15, tc = wt >> 4;           // compute coords

    const float* apA = (wg == 0 ? A0 : A1) + ak0 * BB + ar;
    const float* w0p[3]; const float* w1p[3];       // wg0: Whh0 + Wih1; wg1: Whh1 (w0p)
#pragma unroll
    for (int g = 0; g < 3; g++) {
        const float* W = (wg == 0) ? Whh0 : Whh1;
        w0p[g] = W + ((unsigned)(g * HH + j0 + bcol)) * HH + bkk;
        w1p[g] = Wih1 + ((unsigned)(g * HH + j0 + bcol)) * HH + bkk;
    }

    const u32 smA0 = (u32)__cvta_generic_to_shared(&sm.As0[0][0][0]);
    const u32 smA1 = (u32)__cvta_generic_to_shared(&sm.As1[0][0][0]);
    const u32 smB  = (u32)__cvta_generic_to_shared(&sm.u.Bs[0][0][0][0][0]);

    u64 acc0[6] = {0,0,0,0,0,0};     // wg0: Whh0 / wg1: unused
    u64 accR[2] = {0,0};             // wg0: Wih1 r-gate
    u64 acc1[6] = {0,0,0,0,0,0};     // wg1: Wih1 z,n (slots 2..5)
    u64 acc2[6] = {0,0,0,0,0,0};     // wg1: Whh1

    float pa[4], pbX[3], pbY[3];

    // prologue: chunk 0
#pragma unroll
    for (int q = 0; q < 4; q++) pa[q] = apA[4 * q * BB];
#pragma unroll
    for (int g = 0; g < 3; g++) {
        pbX[g] = __ldg(w0p[g]);
        if (wg == 0) pbY[g] = __ldg(w1p[g]);
    }
    {
        float* Ab = (wg == 0) ? &sm.As0[0][0][0] : &sm.As1[0][0][0];
#pragma unroll
        for (int q = 0; q < 4; q++) Ab[(ak0 + 4 * q) * 64 + ar] = pa[q];
        if (wg == 0) {
            sm.u.Bs[0][0][bcol][bkk][0] = pbX[0];
            sm.u.Bs[0][0][bcol][bkk][1] = pbX[1];
            sm.u.Bs[0][0][bcol][bkk][2] = pbX[2];
            sm.u.Bs[1][0][bcol][bkk][2] = pbY[0];   // r -> slot2
            sm.u.Bs[1][0][bcol][bkk][0] = pbY[1];   // z -> slot0
            sm.u.Bs[1][0][bcol][bkk][1] = pbY[2];   // n -> slot1
        } else {
            sm.u.Bs[2][0][bcol][bkk][0] = pbX[0];
            sm.u.Bs[2][0][bcol][bkk][1] = pbX[1];
            sm.u.Bs[2][0][bcol][bkk][2] = pbX[2];
        }
    }
    __syncthreads();

    for (int kc = 0; kc < 32; ++kc) {
        const int cur = kc & 1;
        if (kc + 1 < 32) {
            const int kb = (kc + 1) * KC;
#pragma unroll
            for (int q = 0; q < 4; q++) pa[q] = apA[(kb + 4 * q) * BB];
#pragma unroll
            for (int g = 0; g < 3; g++) {
                pbX[g] = __ldg(w0p[g] + kb);
                if (wg == 0) pbY[g] = __ldg(w1p[g] + kb);
            }
        }
        const u32 aA0 = smA0 + cur * 4096 + tr * 16;
        const u32 aA1 = smA1 + cur * 4096 + tr * 16;
        const u32 aB0 = smB + (0 + cur) * 4096 + tc * 256;
        const u32 aB1 = smB + (2 + cur) * 4096 + tc * 256;
        const u32 aB2 = smB + (4 + cur) * 4096 + tc * 256;
        if (wg == 0) {
#pragma unroll
            for (int kk = 0; kk < KC; ++kk) {
                u64 al, ah;
                lds_v2u64(al, ah, aA0 + kk * 256);
                u32 x, y, z, w;
                lds_v4u32(x, y, z, w, aB0 + kk * 16);
                u32 r1 = lds_u32(aB1 + kk * 16 + 8);
                u64 br = pack2(x), bz = pack2(y), bn = pack2(z), b1 = pack2(r1);
                ffma2(acc0[0], al, br); ffma2(acc0[1], ah, br);
                ffma2(acc0[2], al, bz); ffma2(acc0[3], ah, bz);
                ffma2(acc0[4], al, bn); ffma2(acc0[5], ah, bn);
                ffma2(accR[0], al, b1); ffma2(accR[1], ah, b1);
            }
        } else {
#pragma unroll
            for (int kk = 0; kk < KC; ++kk) {
                u64 al, ah, cl, ch;
                lds_v2u64(al, ah, aA0 + kk * 256);
                lds_v2u64(cl, ch, aA1 + kk * 256);
                u32 x, y, z, w;
                lds_v4u32(x, y, z, w, aB2 + kk * 16);
                u32 z1, n1;
                lds_v2u32(z1, n1, aB1 + kk * 16);
                u64 br = pack2(x), bz = pack2(y), bn = pack2(z);
                u64 bz1 = pack2(z1), bn1 = pack2(n1);
                ffma2(acc2[0], cl, br); ffma2(acc2[1], ch, br);
                ffma2(acc2[2], cl, bz); ffma2(acc2[3], ch, bz);
                ffma2(acc2[4], cl, bn); ffma2(acc2[5], ch, bn);
                ffma2(acc1[2], al, bz1); ffma2(acc1[3], ah, bz1);
                ffma2(acc1[4], al, bn1); ffma2(acc1[5], ah, bn1);
            }
        }
        if (kc + 1 < 32) {
            const int nxt = (kc + 1) & 1;
            float* Ab = (wg == 0) ? &sm.As0[nxt][0][0] : &sm.As1[nxt][0][0];
#pragma unroll
            for (int q = 0; q < 4; q++) Ab[(ak0 + 4 * q) * 64 + ar] = pa[q];
            if (wg == 0) {
                sm.u.Bs[0][nxt][bcol][bkk][0] = pbX[0];
                sm.u.Bs[0][nxt][bcol][bkk][1] = pbX[1];
                sm.u.Bs[0][nxt][bcol][bkk][2] = pbX[2];
                sm.u.Bs[1][nxt][bcol][bkk][2] = pbY[0];
                sm.u.Bs[1][nxt][bcol][bkk][0] = pbY[1];
                sm.u.Bs[1][nxt][bcol][bkk][1] = pbY[2];
            } else {
                sm.u.Bs[2][nxt][bcol][bkk][0] = pbX[0];
                sm.u.Bs[2][nxt][bcol][bkk][1] = pbX[1];
                sm.u.Bs[2][nxt][bcol][bkk][2] = pbX[2];
            }
        }
        __syncthreads();
    }

    // exchange wg0's Wih1 r-gate accumulators -> wg1, then apply cells
    if (wg == 0) {
        sm.u.xch[wt][0] = accR[0];
        sm.u.xch[wt][1] = accR[1];
    }
    __syncthreads();
    if (wg == 0) {
        if (p < CTXL) cell0_reg(sm, acc0, src, dst, b0, j0, wt);
    } else {
        if (p >= 1) {
            acc1[0] = sm.u.xch[wt][0];
            acc1[1] = sm.u.xch[wt][1];
            cell1_reg(sm, acc1, acc2, src, dst, b0, j0, wt);
        }
    }
}

// ---------------- kernel 3: decode layer0 (head fused; K-split GEMM) ---------------------------
__global__ void __launch_bounds__(NTHR2)
k_dec0(const float* __restrict__ Wih0, const float* __restrict__ Whh0,
       const float* __restrict__ bih0, const float* __restrict__ bhh0,
       const float* __restrict__ Wout, const float* __restrict__ bout,
       float* __restrict__ out, int d, int c0, int c1)
{
    __shared__ Smem sm;
    const int tid = threadIdx.x;
    const int wg = tid >> 8;
    const int wt = tid & 255;
    const int bid = blockIdx.x;
    const int b0 = (bid >> 5) * 64;
    const int j0 = (bid & 31) * 16;

    if (tid < 48) {
        int g = (tid >> 4) * HH + j0 + (tid & 15);
        sm.wih0[tid]  = Wih0[g];
        sm.bih0s[tid] = bih0[g];
        sm.bhh0s[tid] = bhh0[g];
    }

    // head on h1[c1] (512 threads: rr = tid>>3, 8 K-segments of 64)
    {
        const int rr = tid >> 3;
        const int kq = tid & 7;
        const float* h1src = &g_h1[c1][0][0];
        float s = 0.f;
        const int kbase = kq * 64;
#pragma unroll 4
        for (int i = 0; i < 64; ++i) {
            int k = kbase + i;
            s = fmaf(__ldcg(&h1src[k * BB + b0 + rr]), __ldg(&Wout[k]), s);
        }
        s += __shfl_xor_sync(0xffffffffu, s, 1);
        s += __shfl_xor_sync(0xffffffffu, s, 2);
        s += __shfl_xor_sync(0xffffffffu, s, 4);
        if (kq == 0) sm.xv[rr] = s + __ldg(&bout[0]);
        __syncthreads();
        if (j0 == 0 && kq == 0)
            out[(b0 + rr) * PREDL + (d - 1)] = sm.xv[rr] * g_scale[b0 + rr];
    }

    // K-split GEMM: wg g covers K [g*256, g*256+256)
    const float* A0 = &g_h0[c0][0][b0];
    const int ar = wt & 63, ak0 = wt >> 6;
    const int bcol = wt >> 4, bkk = wt & 15;
    const int tr = wt & 15, tc = wt >> 4;
    const int koff = wg * 256;

    const float* apA = A0 + (koff + ak0) * BB + ar;
    const float* wp[3];
#pragma unroll
    for (int g = 0; g < 3; g++)
        wp[g] = Whh0 + ((unsigned)(g * HH + j0 + bcol)) * HH + koff + bkk;

    const u32 smA = (u32)__cvta_generic_to_shared(wg == 0 ? &sm.As0[0][0][0] : &sm.As1[0][0][0]);
    const u32 smB = (u32)__cvta_generic_to_shared(&sm.u.Bs[0][0][0][0][0]) + wg * 8192;

    u64 acc0[6] = {0,0,0,0,0,0};
    float pa[4], pb[3];

#pragma unroll
    for (int q = 0; q < 4; q++) pa[q] = apA[4 * q * BB];
#pragma unroll
    for (int g = 0; g < 3; g++) pb[g] = __ldg(wp[g]);
    {
        float* Ab = (wg == 0) ? &sm.As0[0][0][0] : &sm.As1[0][0][0];
#pragma unroll
        for (int q = 0; q < 4; q++) Ab[(ak0 + 4 * q) * 64 + ar] = pa[q];
        sm.u.Bs[wg][0][bcol][bkk][0] = pb[0];
        sm.u.Bs[wg][0][bcol][bkk][1] = pb[1];
        sm.u.Bs[wg][0][bcol][bkk][2] = pb[2];
    }
    __syncthreads();

    for (int kc = 0; kc < 16; ++kc) {
        const int cur = kc & 1;
        if (kc + 1 < 16) {
            const int kb = (kc + 1) * KC;
#pragma unroll
            for (int q = 0; q < 4; q++) pa[q] = apA[(kb + 4 * q) * BB];
#pragma unroll
            for (int g = 0; g < 3; g++) pb[g] = __ldg(wp[g] + kb);
        }
        const u32 aA = smA + cur * 4096 + tr * 16;
        const u32 aB = smB + cur * 4096 + tc * 256;
#pragma unroll
        for (int kk = 0; kk < KC; ++kk) {
            u64 al, ah;
            lds_v2u64(al, ah, aA + kk * 256);
            u32 x, y, z, w;
            lds_v4u32(x, y, z, w, aB + kk * 16);
            u64 br = pack2(x), bz = pack2(y), bn = pack2(z);
            ffma2(acc0[0], al, br); ffma2(acc0[1], ah, br);
            ffma2(acc0[2], al, bz); ffma2(acc0[3], ah, bz);
            ffma2(acc0[4], al, bn); ffma2(acc0[5], ah, bn);
        }
        if (kc + 1 < 16) {
            const int nxt = (kc + 1) & 1;
            float* Ab = (wg == 0) ? &sm.As0[nxt][0][0] : &sm.As1[nxt][0][0];
#pragma unroll
            for (int q = 0; q < 4; q++) Ab[(ak0 + 4 * q) * 64 + ar] = pa[q];
            sm.u.Bs[wg][nxt][bcol][bkk][0] = pb[0];
            sm.u.Bs[wg][nxt][bcol][bkk][1] = pb[1];
            sm.u.Bs[wg][nxt][bcol][bkk][2] = pb[2];
        }
        __syncthreads();
    }

    if (wg == 1) {
#pragma unroll
        for (int i = 0; i < 6; i++) sm.u.xch[wt][i] = acc0[i];
    }
    __syncthreads();
    if (wg == 0) {
#pragma unroll
        for (int i = 0; i < 6; i++) acc0[i] = addf2(acc0[i], sm.u.xch[wt][i]);
        cell0_reg(sm, acc0, c0, c0 ^ 1, b0, j0, wt);
    }
}

// ---------------- kernel 4: decode layer1 (one GEMM per warp-group) ----------------------------
__global__ void __launch_bounds__(NTHR2)
k_dec1(const float* __restrict__ Wih1, const float* __restrict__ Whh1,
       const float* __restrict__ bih1, const float* __restrict__ bhh1,
       int h0buf, int c1)
{
    __shared__ Smem sm;
    const int tid = threadIdx.x;
    const int wg = tid >> 8;
    const int wt = tid & 255;
    const int bid = blockIdx.x;
    const int b0 = (bid >> 5) * 64;
    const int j0 = (bid & 31) * 16;

    if (tid < 48) {
        int g = (tid >> 4) * HH + j0 + (tid & 15);
        sm.bih1s[tid] = bih1[g];
        sm.bhh1s[tid] = bhh1[g];
    }

    const int ar = wt & 63, ak0 = wt >> 6;
    const int bcol = wt >> 4, bkk = wt & 15;
    const int tr = wt & 15, tc = wt >> 4;

    const float* apA = (wg == 0 ? &g_h0[h0buf][0][b0] : &g_h1[c1][0][b0]) + ak0 * BB + ar;
    const float* wp[3];
#pragma unroll
    for (int g = 0; g < 3; g++) {
        const float* W = (wg == 0) ? Wih1 : Whh1;
        wp[g] = W + ((unsigned)(g * HH + j0 + bcol)) * HH + bkk;
    }

    const u32 smA = (u32)__cvta_generic_to_shared(wg == 0 ? &sm.As0[0][0][0] : &sm.As1[0][0][0]);
    const u32 smB = (u32)__cvta_generic_to_shared(&sm.u.Bs[0][0][0][0][0]) + wg * 8192;

    u64 acc[6] = {0,0,0,0,0,0};
    float pa[4], pb[3];

#pragma unroll
    for (int q = 0; q < 4; q++) pa[q] = apA[4 * q * BB];
#pragma unroll
    for (int g = 0; g < 3; g++) pb[g] = __ldg(wp[g]);
    {
        float* Ab = (wg == 0) ? &sm.As0[0][0][0] : &sm.As1[0][0][0];
#pragma unroll
        for (int q = 0; q < 4; q++) Ab[(ak0 + 4 * q) * 64 + ar] = pa[q];
        sm.u.Bs[wg][0][bcol][bkk][0] = pb[0];
        sm.u.Bs[wg][0][bcol][bkk][1] = pb[1];
        sm.u.Bs[wg][0][bcol][bkk][2] = pb[2];
    }
    __syncthreads();

    for (int kc = 0; kc < 32; ++kc) {
        const int cur = kc & 1;
        if (kc + 1 < 32) {
            const int kb = (kc + 1) * KC;
#pragma unroll
            for (int q = 0; q < 4; q++) pa[q] = apA[(kb + 4 * q) * BB];
#pragma unroll
            for (int g = 0; g < 3; g++) pb[g] = __ldg(wp[g] + kb);
        }
        const u32 aA = smA + cur * 4096 + tr * 16;
        const u32 aB = smB + cur * 4096 + tc * 256;
#pragma unroll
        for (int kk = 0; kk < KC; ++kk) {
            u64 al, ah;
            lds_v2u64(al, ah, aA + kk * 256);
            u32 x, y, z, w;
            lds_v4u32(x, y, z, w, aB + kk * 16);
            u64 br = pack2(x), bz = pack2(y), bn = pack2(z);
            ffma2(acc[0], al, br); ffma2(acc[1], ah, br);
            ffma2(acc[2], al, bz); ffma2(acc[3], ah, bz);
            ffma2(acc[4], al, bn); ffma2(acc[5], ah, bn);
        }
        if (kc + 1 < 32) {
            const int nxt = (kc + 1) & 1;
            float* Ab = (wg == 0) ? &sm.As0[nxt][0][0] : &sm.As1[nxt][0][0];
#pragma unroll
            for (int q = 0; q < 4; q++) Ab[(ak0 + 4 * q) * 64 + ar] = pa[q];
            sm.u.Bs[wg][nxt][bcol][bkk][0] = pb[0];
            sm.u.Bs[wg][nxt][bcol][bkk][1] = pb[1];
            sm.u.Bs[wg][nxt][bcol][bkk][2] = pb[2];
        }
        __syncthreads();
    }

    if (wg == 0) {
#pragma unroll
        for (int i = 0; i < 6; i++) sm.u.xch[wt][i] = acc[i];
    }
    __syncthreads();
    if (wg == 1) {
        u64 acc1[6];
#pragma unroll
        for (int i = 0; i < 6; i++) acc1[i] = sm.u.xch[wt][i];
        cell1_reg(sm, acc1, acc, c1, c1 ^ 1, b0, j0, wt);
    }
}

// ---------------- kernel 5: final head ---------------------------------------------------------
__global__ void __launch_bounds__(NTHR)
k_head(const float* __restrict__ Wout, const float* __restrict__ bout,
       float* __restrict__ out, int c1)
{
    const int tid = threadIdx.x;
    const int b0 = blockIdx.x * 64;
    const int rr = tid >> 2;
    const int kq = tid & 3;
    const float* h1src = &g_h1[c1][0][0];
    float s = 0.f;
    const int kbase = kq * 128;
#pragma unroll 4
    for (int i = 0; i < 128; ++i) {
        int k = kbase + i;
        s = fmaf(__ldcg(&h1src[k * BB + b0 + rr]), __ldg(&Wout[k]), s);
    }
    s += __shfl_xor_sync(0xffffffffu, s, 1);
    s += __shfl_xor_sync(0xffffffffu, s, 2);
    if (kq == 0)
        out[(b0 + rr) * PREDL + (PREDL - 1)] = (s + __ldg(&bout[0])) * g_scale[b0 + rr];
}

extern "C" void kernel_launch(void* const* d_in, const int* in_sizes, int n_in,
                              void* d_out, int out_size)
{
    const float* ctx  = (const float*)d_in[0];
    const float* Wih0 = (const float*)d_in[1];
    const float* Whh0 = (const float*)d_in[2];
    const float* bih0 = (const float*)d_in[3];
    const float* bhh0 = (const float*)d_in[4];
    const float* Wih1 = (const float*)d_in[5];
    const float* Whh1 = (const float*)d_in[6];
    const float* bih1 = (const float*)d_in[7];
    const float* bhh1 = (const float*)d_in[8];
    const float* Wout = (const float*)d_in[9];
    const float* bout = (const float*)d_in[10];
    float* out = (float*)d_out;

    k_init<<<GRID_X, NTHR>>>(ctx);

    for (int p = 0; p <= CTXL; ++p)
        k_enc<<<GRID_X, NTHR2>>>(ctx, Wih0, Whh0, bih0, bhh0,
                                 Wih1, Whh1, bih1, bhh1, p);

    int c0 = 1, c1 = 0;
    for (int d = 1; d < PREDL; ++d) {
        k_dec0<<<GRID_X, NTHR2>>>(Wih0, Whh0, bih0, bhh0, Wout, bout, out, d, c0, c1);
        c0 ^= 1;
        k_dec1<<<GRID_X, NTHR2>>>(Wih1, Whh1, bih1, bhh1, c0, c1);
        c1 ^= 1;
    }
    k_head<<<4, NTHR>>>(Wout, bout, out, c1);
}